// round 7
// baseline (speedup 1.0000x reference)
#include <cuda_runtime.h>
#include <cstdint>

// SparseBMM: C[b] = A[b] @ B[b]
//  A: [8, 4096, 4096] f32, ~80% of 128x128 tiles exactly zero
//  B: [8, 4096, 128] f32;  C: [8, 4096, 128] f32
//
// Round 7: round-6 structure with TWO fixes:
//  1. "memory" clobbers on all cp.async asm — without them the compiler
//     hoisted the nz-check smem loads above cp.async.wait_group, the check
//     read garbage, flag was always true, and the kernel computed DENSELY
//     (that was the whole 830us regression).
//  2. 4-stage A pipeline (prefetch distance 3) so zero-tile runs stream at
//     bandwidth instead of paying one DRAM latency per step.

#define BATCHES 8
#define MDIM    4096
#define KDIM    4096
#define NDIM    128
#define MT      64
#define KT      32
#define KSTEPS  (KDIM / KT)     // 128
#define NTHREADS 128
#define STAGES  4

#define A_TILE  (MT * KT)       // 2048 floats = 8KB
#define B_TILE  (KT * NDIM)     // 4096 floats = 16KB
#define SMEM_FLOATS (STAGES * A_TILE + B_TILE)
#define SMEM_BYTES  (SMEM_FLOATS * 4)   // 48KB

__device__ __forceinline__ void cp_async16(uint32_t dst_smem, const float* src) {
    asm volatile("cp.async.cg.shared.global [%0], [%1], 16;"
                 :: "r"(dst_smem), "l"(src) : "memory");
}
__device__ __forceinline__ void cp_commit() {
    asm volatile("cp.async.commit_group;" ::: "memory");
}
__device__ __forceinline__ void cp_wait_3() {
    asm volatile("cp.async.wait_group 3;" ::: "memory");
}

__global__ __launch_bounds__(NTHREADS, 4)
void sparse_bmm_kernel(const float* __restrict__ A,
                       const float* __restrict__ B,
                       float* __restrict__ C) {
    extern __shared__ float sm[];
    float* Bs = sm + STAGES * A_TILE;   // B tile: [32][128] f32

    const int bidx  = blockIdx.x;       // 0..511
    const int batch = bidx >> 6;
    const int mt    = bidx & 63;

    const float* Ag = A + (size_t)batch * MDIM * KDIM + (size_t)mt * MT * KDIM;
    const float* Bg = B + (size_t)batch * KDIM * NDIM;
    float*       Cg = C + (size_t)batch * MDIM * NDIM + (size_t)mt * MT * NDIM;

    const int tid = threadIdx.x;
    const int tx  = tid & 15;           // 8 output cols each
    const int ty  = tid >> 4;           // 8 output rows each

    // cp.async geometry: 512 16B-chunks per A tile; thread handles chunks
    // (tid + 128*t), t<4: row = (tid>>3) + 16*t, float4-col = tid&7.
    const int arow = tid >> 3;
    const int acol = tid & 7;

    const uint32_t sa_base  = (uint32_t)__cvta_generic_to_shared(sm);
    const uint32_t a_sm_off = (uint32_t)(arow * KT + acol * 4) * 4;
    const float*   a_gm     = Ag + (size_t)arow * KDIM + acol * 4;

    unsigned long long acc[8][4];
#pragma unroll
    for (int i = 0; i < 8; i++)
#pragma unroll
        for (int p = 0; p < 4; p++) acc[i][p] = 0ull;

    // ---- prologue: async-load tiles 0..2 into stages 0..2 ----
#pragma unroll
    for (int s = 0; s < STAGES - 1; s++) {
        const uint32_t sdst = sa_base + (uint32_t)(s * A_TILE) * 4 + a_sm_off;
        const float*   src  = a_gm + (size_t)s * KT;
#pragma unroll
        for (int t = 0; t < 4; t++)
            cp_async16(sdst + (uint32_t)(t * 16 * KT) * 4,
                       src + (size_t)(t * 16) * KDIM);
        cp_commit();
    }

    for (int kt = 0; kt < KSTEPS; kt++) {
        const int stage = kt & (STAGES - 1);
        const float* Acur = sm + stage * A_TILE;

        // ---- issue async load of tile kt+3 into stage (kt+3)&3 ----
        // That buffer held tile kt-1, fully consumed in step kt-1 (nz reads
        // are same-thread same-address; compute ends with __syncthreads).
        if (kt + STAGES - 1 < KSTEPS) {
            const int nstage = (kt + STAGES - 1) & (STAGES - 1);
            const uint32_t sdst = sa_base + (uint32_t)(nstage * A_TILE) * 4 + a_sm_off;
            const float* src = a_gm + (size_t)(kt + STAGES - 1) * KT;
#pragma unroll
            for (int t = 0; t < 4; t++)
                cp_async16(sdst + (uint32_t)(t * 16 * KT) * 4,
                           src + (size_t)(t * 16) * KDIM);
        }
        cp_commit();   // exactly one group per iteration -> wait_group 3 exact

        // ---- tile kt complete after wait; nz-check own chunks ----
        cp_wait_3();
        unsigned nz = 0;
#pragma unroll
        for (int t = 0; t < 4; t++) {
            const uint4 v = *(const uint4*)(Acur + (arow + t * 16) * KT + acol * 4);
            nz |= v.x | v.y | v.z | v.w;
        }
        // Barrier: all threads waited -> whole tile visible to all; also
        // orders step kt-1's reads before the next overwrite of its buffer.
        const int flag = __syncthreads_or(nz != 0u);

        if (flag) {
            // ---- stage B tile [32][128] (L2-resident, reused by 64 CTAs) ----
            const float4* Bsrc = (const float4*)(Bg + (size_t)kt * KT * NDIM);
            float4* Bdst = (float4*)Bs;
#pragma unroll
            for (int t = 0; t < 8; t++)
                Bdst[tid + t * NTHREADS] = Bsrc[tid + t * NTHREADS];
            __syncthreads();

            // ---- compute: scalar A broadcast + packed FFMA2 ----
            const float* ar = Acur + (ty * 8) * KT;
#pragma unroll 8
            for (int kk = 0; kk < KT; kk++) {
                unsigned long long bb[4];
                const unsigned long long* bp =
                    (const unsigned long long*)(Bs + kk * NDIM + tx * 8);
#pragma unroll
                for (int p = 0; p < 4; p++) bb[p] = bp[p];

                unsigned long long aa[8];
#pragma unroll
                for (int i = 0; i < 8; i++) {
                    float a = ar[i * KT + kk];
                    asm("mov.b64 %0, {%1, %1};" : "=l"(aa[i]) : "f"(a));
                }
#pragma unroll
                for (int i = 0; i < 8; i++)
#pragma unroll
                    for (int p = 0; p < 4; p++)
                        asm("fma.rn.f32x2 %0, %1, %2, %0;"
                            : "+l"(acc[i][p])
                            : "l"(aa[i]), "l"(bb[p]));
            }
            // Protect Acur and Bs from the next overwrite.
            __syncthreads();
        }
    }

    // ---- epilogue ----
#pragma unroll
    for (int i = 0; i < 8; i++) {
        float* crow = Cg + (size_t)(ty * 8 + i) * NDIM + tx * 8;
#pragma unroll
        for (int p = 0; p < 4; p++)
            *(unsigned long long*)(crow + p * 2) = acc[i][p];
    }
}

extern "C" void kernel_launch(void* const* d_in, const int* in_sizes, int n_in,
                              void* d_out, int out_size) {
    const float* a = (const float*)d_in[0];
    const float* b = (const float*)d_in[1];
    float* c = (float*)d_out;

    cudaFuncSetAttribute(sparse_bmm_kernel,
                         cudaFuncAttributeMaxDynamicSharedMemorySize,
                         SMEM_BYTES);

    dim3 grid(BATCHES * (MDIM / MT));   // 512 CTAs
    sparse_bmm_kernel<<<grid, NTHREADS, SMEM_BYTES>>>(a, b, c);
}

// round 8
// speedup vs baseline: 3.6384x; 3.6384x over previous
#include <cuda_runtime.h>
#include <cstdint>

// SparseBMM: C[b] = A[b] @ B[b]
//  A: [8, 4096, 4096] f32, ~80% of 128x128 tiles exactly zero (incl. -0.0!)
//  B: [8, 4096, 128] f32;  C: [8, 4096, 128] f32
//
// Round 8 fixes vs round 7:
//  1. THE BUG: reference zeros are a*mask -> negative values produce -0.0
//     (0x80000000). The integer-OR nonzero check saw -0.0 as nonzero, so
//     flag was ALWAYS true and rounds 5-7 computed densely (466us fma-busy
//     = dense floor). Fix: mask the sign bit before testing.
//  2. LDS bank conflicts (round 1's limiter, L1=56%): A smem XOR-swizzled
//     by row>>3 (read-side constant per thread); B per-thread columns
//     remapped to pairs tx*2 + 32p so each LDS.64 covers all 32 banks.

#define BATCHES 8
#define MDIM    4096
#define KDIM    4096
#define NDIM    128
#define MT      64
#define KT      32
#define KSTEPS  (KDIM / KT)     // 128
#define NTHREADS 128
#define STAGES  4

#define A_TILE  (MT * KT)       // 2048 floats = 8KB
#define B_TILE  (KT * NDIM)     // 4096 floats = 16KB
#define SMEM_FLOATS (STAGES * A_TILE + B_TILE)
#define SMEM_BYTES  (SMEM_FLOATS * 4)   // 48KB

__device__ __forceinline__ void cp_async16(uint32_t dst_smem, const float* src) {
    asm volatile("cp.async.cg.shared.global [%0], [%1], 16;"
                 :: "r"(dst_smem), "l"(src) : "memory");
}
__device__ __forceinline__ void cp_commit() {
    asm volatile("cp.async.commit_group;" ::: "memory");
}
__device__ __forceinline__ void cp_wait_3() {
    asm volatile("cp.async.wait_group 3;" ::: "memory");
}

__global__ __launch_bounds__(NTHREADS, 4)
void sparse_bmm_kernel(const float* __restrict__ A,
                       const float* __restrict__ B,
                       float* __restrict__ C) {
    extern __shared__ float sm[];
    float* Bs = sm + STAGES * A_TILE;   // B tile: [32][128] f32

    const int bidx  = blockIdx.x;       // 0..511
    const int batch = bidx >> 6;
    const int mt    = bidx & 63;

    const float* Ag = A + (size_t)batch * MDIM * KDIM + (size_t)mt * MT * KDIM;
    const float* Bg = B + (size_t)batch * KDIM * NDIM;
    float*       Cg = C + (size_t)batch * MDIM * NDIM + (size_t)mt * MT * NDIM;

    const int tid = threadIdx.x;
    const int tx  = tid & 15;           // col group
    const int ty  = tid >> 4;           // row group (8 rows: ty*8 .. ty*8+7)

    // cp.async geometry: thread handles chunks row = (tid>>3) + 16t, col4 = tid&7.
    const int arow = tid >> 3;
    const int acol = tid & 7;
    const int aq   = arow >> 3;         // 0 or 1

    const uint32_t sa_base = (uint32_t)__cvta_generic_to_shared(sm);
    const float*   a_gm    = Ag + (size_t)arow * KDIM + acol * 4;

    // Swizzled smem float-offset of thread's chunk t within an A tile:
    // row = arow + 16t, swizzle = row>>3 = aq + 2t
    unsigned a_off[4];
#pragma unroll
    for (int t = 0; t < 4; t++)
        a_off[t] = (unsigned)((arow + 16 * t) * KT + ((acol ^ (aq + 2 * t)) << 2));

    unsigned long long acc[8][4];
#pragma unroll
    for (int i = 0; i < 8; i++)
#pragma unroll
        for (int p = 0; p < 4; p++) acc[i][p] = 0ull;

    // ---- prologue: async-load tiles 0..2 into stages 0..2 ----
#pragma unroll
    for (int s = 0; s < STAGES - 1; s++) {
        const uint32_t sdst = sa_base + (uint32_t)(s * A_TILE) * 4;
        const float*   src  = a_gm + (size_t)s * KT;
#pragma unroll
        for (int t = 0; t < 4; t++)
            cp_async16(sdst + a_off[t] * 4, src + (size_t)(t * 16) * KDIM);
        cp_commit();
    }

    for (int kt = 0; kt < KSTEPS; kt++) {
        const int stage = kt & (STAGES - 1);
        const float* Acur = sm + stage * A_TILE;

        // ---- issue async load of tile kt+3 ----
        if (kt + STAGES - 1 < KSTEPS) {
            const int nstage = (kt + STAGES - 1) & (STAGES - 1);
            const uint32_t sdst = sa_base + (uint32_t)(nstage * A_TILE) * 4;
            const float* src = a_gm + (size_t)(kt + STAGES - 1) * KT;
#pragma unroll
            for (int t = 0; t < 4; t++)
                cp_async16(sdst + a_off[t] * 4, src + (size_t)(t * 16) * KDIM);
        }
        cp_commit();   // one group per iteration -> wait_group 3 is exact

        // ---- tile kt complete; nz-check own chunks (SIGN-MASKED) ----
        cp_wait_3();
        unsigned nzw = 0;
#pragma unroll
        for (int t = 0; t < 4; t++) {
            const uint4 v = *(const uint4*)(Acur + a_off[t]);
            nzw |= v.x | v.y | v.z | v.w;
        }
        // -0.0 (0x80000000) must count as zero: clear the accumulated sign bit.
        const int flag = __syncthreads_or((nzw & 0x7FFFFFFFu) != 0u);

        if (flag) {
            // ---- stage B tile [32][128] (L2-resident, reused by 64 CTAs) ----
            const float4* Bsrc = (const float4*)(Bg + (size_t)kt * KT * NDIM);
            float4* Bdst = (float4*)Bs;
#pragma unroll
            for (int t = 0; t < 8; t++)
                Bdst[tid + t * NTHREADS] = Bsrc[tid + t * NTHREADS];
            __syncthreads();

            // ---- compute: A swizzled broadcast + bank-spread B + FFMA2 ----
            const float* ar = Acur + (ty * 8) * KT;
#pragma unroll 8
            for (int kk = 0; kk < KT; kk++) {
                // B pairs at float cols tx*2 + 32p: LDS.64 hits all 32 banks once
                unsigned long long bb[4];
                const float* brow = Bs + kk * NDIM + tx * 2;
#pragma unroll
                for (int p = 0; p < 4; p++)
                    bb[p] = *(const unsigned long long*)(brow + 32 * p);

                // A element for row ty*8+i at swizzled column
                const int asw = ((((kk >> 2) ^ ty) & 7) << 2) + (kk & 3);
                unsigned long long aa[8];
#pragma unroll
                for (int i = 0; i < 8; i++) {
                    float a = ar[i * KT + asw];
                    asm("mov.b64 %0, {%1, %1};" : "=l"(aa[i]) : "f"(a));
                }
#pragma unroll
                for (int i = 0; i < 8; i++)
#pragma unroll
                    for (int p = 0; p < 4; p++)
                        asm("fma.rn.f32x2 %0, %1, %2, %0;"
                            : "+l"(acc[i][p])
                            : "l"(aa[i]), "l"(bb[p]));
            }
            // Protect Acur and Bs from the next overwrite.
            __syncthreads();
        }
    }

    // ---- epilogue: pair p of row i goes to cols tx*2 + 32p ----
#pragma unroll
    for (int i = 0; i < 8; i++) {
        float* crow = Cg + (size_t)(ty * 8 + i) * NDIM + tx * 2;
#pragma unroll
        for (int p = 0; p < 4; p++)
            *(unsigned long long*)(crow + 32 * p) = acc[i][p];
    }
}

extern "C" void kernel_launch(void* const* d_in, const int* in_sizes, int n_in,
                              void* d_out, int out_size) {
    const float* a = (const float*)d_in[0];
    const float* b = (const float*)d_in[1];
    float* c = (float*)d_out;

    cudaFuncSetAttribute(sparse_bmm_kernel,
                         cudaFuncAttributeMaxDynamicSharedMemorySize,
                         SMEM_BYTES);

    dim3 grid(BATCHES * (MDIM / MT));   // 512 CTAs
    sparse_bmm_kernel<<<grid, NTHREADS, SMEM_BYTES>>>(a, b, c);
}